// round 4
// baseline (speedup 1.0000x reference)
#include <cuda_runtime.h>

#define NN 512          // T = U = 512
#define KD 8            // diagonals per barrier step
#define RB 32           // boundary ring slots per warp (= 4*KD, power of 2)
#define NW 16           // warps per CTA
#define BDIM 512
#define C_CONST 1.0f
#define GEPS 1e-9f
#define MAXB 64

__device__ float g_costs[MAXB];

// trans(x_val, y_prev, z_other): a = x_val - y_prev, b = x_val - z_other, gamma=1
__device__ __forceinline__ float transf(float a, float b) {
    float u = a * b;
    // (1 - gate) = 0.5 * (1 + u / sqrt(u^2 + eps))
    float w = 0.5f * (1.0f + u * rsqrtf(fmaf(u, u, GEPS)));
    float A = a * a;
    float B = b * b;
    float m = fminf(A, B);
    float M = fmaxf(A, B);
    float sm = m - __logf(1.0f + __expf(m - M));   // softmin2(A,B)
    return fmaf(w, sm, C_CONST);
}

__global__ __launch_bounds__(BDIM, 1)
void soft_msm_kernel(const float* __restrict__ x, const float* __restrict__ y) {
    __shared__ float sx[NN];          // x values
    __shared__ float sau[NN];         // x[i] - x[i-1]
    __shared__ float bnd[NW][RB];     // per-warp boundary-column ring (column 32w+31)

    const int b    = blockIdx.x;
    const int tid  = threadIdx.x;
    const int w    = tid >> 5;
    const int lane = tid & 31;
    const int j    = tid;             // column owned by this thread

    const float* xb = x + b * NN;
    const float* yb = y + b * NN;

    const float yj = yb[j];
    const float al = (j > 0) ? (yj - yb[j - 1]) : 0.0f;   // y_j - y_{j-1}

    sx[tid] = xb[tid];
    __syncthreads();
    sau[tid] = (tid > 0) ? (sx[tid] - sx[tid - 1]) : 0.0f;
    const float x0 = sx[0];
    __syncthreads();

    float curC  = 0.0f;   // C[i_prev, j] : own value from previous diagonal
    float pdiag = 0.0f;   // C[i-1, j-1]  : left neighbor's value two diagonals back

    // Warp w processes diagonals [(s-w)*KD, (s-w)*KD + KD) at barrier-step s.
    // Last diag = 1022, done by warp 15 at s = 15 + 1022/KD.
    const int nsteps = (NW - 1) + (2 * NN - 2) / KD + 1;   // 143 for KD=8

    for (int s = 0; s < nsteps; ++s) {
        const int D0 = (s - w) * KD;
        // strip w is touched by diagonals [32w, 32w+31+NN-1]
        if (D0 + (KD - 1) >= 32 * w && D0 <= 32 * w + 31 + (NN - 1)) {
            #pragma unroll
            for (int k = 0; k < KD; ++k) {
                const int D = D0 + k;
                // left neighbor C[i, j-1] lives on diagonal D-1:
                // lane l-1's curC (not yet updated this k-iteration), or the
                // previous warp's boundary ring for lane 0.
                float from_left = __shfl_up_sync(0xffffffffu, curC, 1);
                if (lane == 0 && w > 0) from_left = bnd[w - 1][(D - 1) & (RB - 1)];

                const int i = D - j;
                if (0 <= i && i < NN) {
                    if (i == 0) {
                        if (j == 0) {
                            float d0 = x0 - yj;
                            curC = d0 * d0;                       // C[0,0]
                        } else {
                            // C[0,j] = C[0,j-1] + trans(y_j, y_{j-1}, x_0)
                            curC  = from_left + transf(al, yj - x0);
                            pdiag = from_left;
                        }
                    } else if (j == 0) {
                        // C[i,0] = C[i-1,0] + trans(x_i, x_{i-1}, y_0)
                        float xi = sx[i];
                        curC = curC + transf(sau[i], xi - yj);
                    } else {
                        float xi    = sx[i];
                        float bx    = xi - yj;
                        float match = bx * bx;
                        float up    = transf(sau[i], bx);   // trans(x_i, x_{i-1}, y_j)
                        float left  = transf(al,  -bx);     // trans(y_j, y_{j-1}, x_i)

                        float dd = pdiag     + match;       // diag
                        float du = curC      + up;          // up (own register)
                        float cl = from_left + left;        // left

                        float m = fminf(dd, fminf(du, cl));
                        float ssum = __expf(m - dd) + __expf(m - du) + __expf(m - cl);
                        curC  = m - __logf(ssum);
                        pdiag = from_left;
                    }
                    if (lane == 31) bnd[w][D & (RB - 1)] = curC;
                }
            }
        }
        __syncthreads();
    }

    if (tid == NN - 1) g_costs[b] = curC;   // C[511,511]
}

__global__ void reduce_kernel(float* __restrict__ out, int B) {
    __shared__ float s[MAXB];
    int t = threadIdx.x;
    s[t] = (t < B) ? g_costs[t] : 0.0f;
    __syncthreads();
    for (int off = MAXB / 2; off > 0; off >>= 1) {
        if (t < off) s[t] += s[t + off];
        __syncthreads();
    }
    if (t == 0) out[0] = s[0] * (1.0f / (float)B);
}

extern "C" void kernel_launch(void* const* d_in, const int* in_sizes, int n_in,
                              void* d_out, int out_size) {
    const float* x = (const float*)d_in[0];
    const float* y = (const float*)d_in[1];
    int B = in_sizes[0] / NN;   // 64
    if (B > MAXB) B = MAXB;
    soft_msm_kernel<<<B, BDIM>>>(x, y);
    reduce_kernel<<<1, MAXB>>>((float*)d_out, B);
}

// round 5
// speedup vs baseline: 2.2478x; 2.2478x over previous
#include <cuda_runtime.h>

#define NN 512          // T = U = 512
#define NT 256          // 256 threads, 2 interleaved columns each
#define C_CONST 1.0f
#define GEPS 1e-9f
#define MAXB 64

__device__ float g_costs[MAXB];

// trans with a, b given plus precomputed A=a^2, B=b^2 (B shared with match)
__device__ __forceinline__ float transf(float a, float b, float A, float B) {
    float u = a * b;
    float w = 0.5f * (1.0f + u * rsqrtf(fmaf(u, u, GEPS)));   // 1 - gate
    float mn = fminf(A, B);
    float mx = fmaxf(A, B);
    float sm = mn - __logf(1.0f + __expf(mn - mx));           // softmin2
    return fmaf(w, sm, C_CONST);
}

// softmin3 with the min-arm's exp folded to 1 (exact), INF-safe for boundary arms
__device__ __forceinline__ float softmin3f(float a, float b, float c) {
    float mn    = fminf(a, fminf(b, c));
    float mx    = fmaxf(a, fmaxf(b, c));
    float ab_mn = fminf(a, b);
    float ab_mx = fmaxf(a, b);
    float md    = fmaxf(ab_mn, fminf(ab_mx, c));              // median
    float s = 1.0f + __expf(mn - md) + __expf(mn - mx);       // exp(mn-mn)==1
    return mn - __logf(s);
}

__global__ __launch_bounds__(NT, 1)
void soft_msm_kernel(const float* __restrict__ x, const float* __restrict__ y) {
    __shared__ float sxe[NT], sxo[NT];    // x even / odd indices
    __shared__ float saue[NT], sauo[NT];  // sau[i] = x[i]-x[i-1], split by parity of i
    __shared__ float bnd[8][2];           // per-warp boundary col (64w+63), double-buffered

    const int b    = blockIdx.x;
    const int t    = threadIdx.x;
    const int w    = t >> 5;
    const int lane = t & 31;
    const float* xb = x + b * NN;
    const float* yb = y + b * NN;

    // column constants: jE = 2t, jO = 2t+1
    const float yE   = yb[2 * t];
    const float yO   = yb[2 * t + 1];
    const float yEm1 = (t > 0) ? yb[2 * t - 1] : 0.0f;
    const float alE  = yE - yEm1;         // y_jE - y_{jE-1}
    const float alO  = yO - yE;
    const float alE2 = alE * alE;
    const float alO2 = alO * alO;

    const float xe = xb[2 * t];
    const float xo = xb[2 * t + 1];
    sxe[t] = xe; sxo[t] = xo;
    __syncthreads();
    saue[t] = (t > 0) ? (xe - sxo[t - 1]) : 0.0f;   // sau[2t]
    sauo[t] = xo - xe;                               // sau[2t+1]
    const float x0 = sxe[0];
    __syncthreads();

    // carried DP state
    float prevE  = 0.0f;   // C[.., jE] @ d-1
    float prevO  = 0.0f;   // C[.., jO] @ d-1
    float prev2E = 0.0f;   // C[.., jE] @ d-2  (diag for odd cell)
    float pdiagE = 0.0f;   // C[.., jE-1] @ d-2 (diag for even cell)
    if (t == 0) { float d0 = x0 - yE; prevE = d0 * d0; }     // C[0,0], diagonal 0

    const int jE = 2 * t;
    const int D0 = 64 * w;                 // warp active for d in [D0, D0+575]
    const float INF = __int_as_float(0x7f800000);

    for (int d = 1; d <= 2 * NN - 2; ++d) {
        if (d >= D0 && d <= D0 + 575) {    // warp-uniform activity window
            // left neighbor of even col on diagonal d-1 = prev thread's odd col
            float fromLeft = __shfl_up_sync(0xffffffffu, prevO, 1);
            if (lane == 0 && w > 0) fromLeft = bnd[w - 1][(d - 1) & 1];

            // parity-split x arrays: parity(iE) == parity(d)
            const float* xEa = (d & 1) ? sxo  : sxe;
            const float* xOa = (d & 1) ? sxe  : sxo;
            const float* sEa = (d & 1) ? sauo : saue;
            const float* sOa = (d & 1) ? saue : sauo;

            const int iE = d - jE;
            const int iO = iE - 1;
            const bool vE = (iE >= 0) && (iE < NN);
            const bool vO = (iO >= 0) && (iO < NN);
            const int iEc = min(max(iE, 0), NN - 1);
            const int iOc = min(max(iO, 0), NN - 1);
            const float xiE = xEa[iEc >> 1];
            const float xiO = xOa[iOc >> 1];
            const float saE = sEa[iEc >> 1];
            const float saO = sOa[iOc >> 1];

            // ---- even cell (iE, jE) ----
            float bxE = xiE - yE;
            float mE  = bxE * bxE;
            float utE = transf(saE,  bxE, saE * saE, mE);   // trans(x_i, x_{i-1}, y_j)
            float ltE = transf(alE, -bxE, alE2,      mE);   // trans(y_j, y_{j-1}, x_i)
            float dd = pdiagE   + mE;
            float du = prevE    + utE;
            float cl = fromLeft + ltE;
            if (jE == 0) { dd = INF; cl = INF; }            // col-0 boundary
            if (iE == 0) { dd = INF; du = INF; }            // row-0 boundary
            float cE = softmin3f(dd, du, cl);

            // ---- odd cell (iO, jO): neighbors are own registers ----
            float bxO = xiO - yO;
            float mO  = bxO * bxO;
            float utO = transf(saO,  bxO, saO * saO, mO);
            float ltO = transf(alO, -bxO, alO2,      mO);
            float ddo = prev2E + mO;
            float duo = prevO  + utO;
            float clo = prevE  + ltO;                       // left = even col @ d-1
            if (iO == 0) { ddo = INF; duo = INF; }
            float cO = softmin3f(ddo, duo, clo);

            // state rotation (compute-then-update; predicated on validity)
            if (vE) { pdiagE = fromLeft; prev2E = prevE; prevE = cE; }
            if (vO) { prevO = cO; }
            if (lane == 31) bnd[w][d & 1] = prevO;
        }
        __syncthreads();
    }

    if (t == NT - 1) g_costs[b] = prevO;   // C[511, 511]
}

__global__ void reduce_kernel(float* __restrict__ out, int B) {
    __shared__ float s[MAXB];
    int t = threadIdx.x;
    s[t] = (t < B) ? g_costs[t] : 0.0f;
    __syncthreads();
    for (int off = MAXB / 2; off > 0; off >>= 1) {
        if (t < off) s[t] += s[t + off];
        __syncthreads();
    }
    if (t == 0) out[0] = s[0] * (1.0f / (float)B);
}

extern "C" void kernel_launch(void* const* d_in, const int* in_sizes, int n_in,
                              void* d_out, int out_size) {
    const float* x = (const float*)d_in[0];
    const float* y = (const float*)d_in[1];
    int B = in_sizes[0] / NN;   // 64
    if (B > MAXB) B = MAXB;
    soft_msm_kernel<<<B, NT>>>(x, y);
    reduce_kernel<<<1, MAXB>>>((float*)d_out, B);
}